// round 15
// baseline (speedup 1.0000x reference)
#include <cuda_runtime.h>
#include <cstdint>
#include <math.h>

#define E_DIM 1024
#define H_HEADS 16
#define D_HEAD 64
#define B_BATCH 4
#define TBQ 1024
#define TWQ 512
#define NH 64            // B_BATCH * H_HEADS
#define NR 33            // 2L+1
#define SCALE_Q 0.125f   // D^-0.5

// ---------------- scratch (device globals; no dynamic allocation) ----------
__device__ float g_qb[(size_t)NH * TBQ * D_HEAD];   // [n, t, d]
__device__ float g_kb[(size_t)NH * TBQ * D_HEAD];   // [n, t, d]
__device__ float g_vT[(size_t)NH * D_HEAD * TBQ];   // [n, d, t]
__device__ float g_qw[(size_t)NH * TWQ * D_HEAD];   // [n, w, d]
__device__ float g_kw[(size_t)NH * TWQ * D_HEAD];   // [n, w, d]
__device__ float g_arb[(size_t)NH * TBQ * NR];      // q_bpe . table
__device__ float g_arw[(size_t)NH * TWQ * NR];      // q_word . table
__device__ float g_awt[(size_t)NH * TWQ * TWQ];     // attn_word TRANSPOSED: [n, s, w]
__device__ float g_G[(size_t)NH * TBQ * TWQ];       // mapping @ attn_word: [n, q, s]
__device__ float g_attn[(size_t)NH * TBQ * TBQ];    // raw logits (256MB)
__device__ float g_ctx[(size_t)NH * TBQ * D_HEAD];  // softmax(attn) @ v
__device__ unsigned g_rowmax[(size_t)NH * TBQ];     // encoded per-row logit max

// ---------------- helpers -----------------------------------------------------
__device__ __forceinline__ uint32_t smem_u32(const void* p) {
    uint32_t a;
    asm("{ .reg .u64 t; cvta.to.shared.u64 t, %1; cvt.u32.u64 %0, t; }"
        : "=r"(a) : "l"(p));
    return a;
}
__device__ __forceinline__ float tf32f(float x) {
    uint32_t r;
    asm("cvt.rna.tf32.f32 %0, %1;" : "=r"(r) : "f"(x));
    return __uint_as_float(r);
}
__device__ __forceinline__ uint32_t tf32b(float x) {
    uint32_t r;
    asm("cvt.rna.tf32.f32 %0, %1;" : "=r"(r) : "f"(x));
    return r;
}
__device__ __forceinline__ int clip_rel(int d) {
    return (d < -16 ? -16 : (d > 16 ? 16 : d)) + 16;
}
// monotone float<->uint encoding for atomicMax on floats
__device__ __forceinline__ unsigned fenc(float x) {
    int b = __float_as_int(x);
    return (b >= 0) ? ((unsigned)b | 0x80000000u) : ~(unsigned)b;
}
__device__ __forceinline__ float fdec(unsigned k) {
    int b = (k & 0x80000000u) ? (int)(k & 0x7FFFFFFFu) : ~(int)k;
    return __int_as_float(b);
}
// streaming 16B copy: L2-only (.cg)
__device__ __forceinline__ void cpa16(uint32_t saddr, const float* gaddr) {
    asm volatile("cp.async.cg.shared.global [%0], [%1], 16;"
                 :: "r"(saddr), "l"(gaddr) : "memory");
}
#define CP_COMMIT() asm volatile("cp.async.commit_group;" ::: "memory")
#define CP_WAIT1() asm volatile("cp.async.wait_group 1;" ::: "memory")
#define CP_WAIT0() asm volatile("cp.async.wait_group 0;" ::: "memory")

// mma.sync tf32 m16n8k8 (baseline PTX -> HMMA on sm_103)
__device__ __forceinline__ void mma8(float* c, const uint32_t* a, const uint32_t* b) {
    asm volatile(
        "mma.sync.aligned.m16n8k8.row.col.f32.tf32.tf32.f32 "
        "{%0,%1,%2,%3}, {%4,%5,%6,%7}, {%8,%9}, {%0,%1,%2,%3};"
        : "+f"(c[0]), "+f"(c[1]), "+f"(c[2]), "+f"(c[3])
        : "r"(a[0]), "r"(a[1]), "r"(a[2]), "r"(a[3]), "r"(b[0]), "r"(b[1]));
}

// packed f32x2 (FFMA2) for the fallback core
__device__ __forceinline__ unsigned long long pk2(float x, float y) {
    unsigned long long r;
    asm("mov.b64 %0, {%1, %2};" : "=l"(r) : "f"(x), "f"(y));
    return r;
}
__device__ __forceinline__ void upk2(unsigned long long v, float& x, float& y) {
    asm("mov.b64 {%0, %1}, %2;" : "=f"(x), "=f"(y) : "l"(v));
}
__device__ __forceinline__ void fma2(unsigned long long& c, unsigned long long a,
                                     unsigned long long b) {
    asm("fma.rn.f32x2 %0, %1, %2, %0;" : "+l"(c) : "l"(a), "l"(b));
}

// ---------------- mma.sync 3xTF32 NT GEMM core v4 (BK=32, pair stores) --------
// C[m][n] = sum_k ta(A[m,k], m_local, j)*B[n,k], ~fp32 via 3xTF32 split.
// M % BM == 0, N % BN == 0, K % 32 == 0. BK = 32.
// pa4/pb4: const float* to 16B chunk (row, k4), global k4 index (k = 4*k4).
// ta(v, local_row, j): A transform; j = compile-time row-slot.
// pe(): after k-loop, before epilogue.
// sc(m, n, v0, v1, j): store PAIR at (m,n),(m,n+1); j = compile-time row-slot.
// smem: raw fp32, 32 floats/row, 3-bit chunk swizzle:
//   chunk' = k4 ^ ((row>>1)&3) ^ ((row&1)<<2)   (conflict-free both sides)
// cp.async double-buffered. NTHR threads.
template <int NTHR, int BM, int BN, int WM, int WN,
          class PA, class PB, class TA, class PE, class SC>
__device__ __forceinline__ void gemm_mma3(int K, PA pa4, PB pb4, TA ta, PE pe, SC sc) {
    constexpr int ASZ = BM * 32;           // floats
    constexpr int BSZ = BN * 32;
    constexpr int BUF = ASZ + BSZ;
    constexpr int ACH = BM * 8;            // 16B chunks
    constexpr int BCH = BN * 8;
    constexpr int MT = WM / 16;
    constexpr int NT = WN / 8;
    constexpr int WGM = BM / WM;
    static_assert((BM / WM) * (BN / WN) == NTHR / 32, "warp grid");
    static_assert(ACH % NTHR == 0 && BCH % NTHR == 0, "fetch split");

    extern __shared__ float smf[];
    const uint32_t sbase = smem_u32(smf);

    const int tid = threadIdx.x;
    const int lane = tid & 31;
    const int wid = tid >> 5;
    const int wm0 = (wid % WGM) * WM;
    const int wn0 = (wid / WGM) * WN;
    const int bm = blockIdx.y * BM;
    const int bn = blockIdx.x * BN;
    const int g = lane >> 2;
    const int t4 = lane & 3;
    const int asw = ((g >> 1) & 3) | ((g & 1) << 2);   // 3-bit frag swizzle mask

    float acc[MT][NT][4];
#pragma unroll
    for (int i = 0; i < MT; i++)
#pragma unroll
        for (int j = 0; j < NT; j++) {
            acc[i][j][0] = 0.f; acc[i][j][1] = 0.f;
            acc[i][j][2] = 0.f; acc[i][j][3] = 0.f;
        }

    const int KT = K / 32;

    auto issue = [&](int kt, int buf) {
        uint32_t ab = sbase + buf * (BUF * 4);
        uint32_t bb = ab + ASZ * 4;
#pragma unroll
        for (int l = 0; l < ACH / NTHR; l++) {
            int f = tid + l * NTHR;
            int row = f >> 3, k4 = f & 7;
            int sw = k4 ^ ((row >> 1) & 3) ^ ((row & 1) << 2);
            cpa16(ab + (row * 8 + sw) * 16, pa4(bm + row, kt * 8 + k4));
        }
#pragma unroll
        for (int l = 0; l < BCH / NTHR; l++) {
            int f = tid + l * NTHR;
            int row = f >> 3, k4 = f & 7;
            int sw = k4 ^ ((row >> 1) & 3) ^ ((row & 1) << 2);
            cpa16(bb + (row * 8 + sw) * 16, pb4(bn + row, kt * 8 + k4));
        }
    };

    issue(0, 0);
    CP_COMMIT();

    for (int kt = 0; kt < KT; kt++) {
        const int cur = kt & 1;
        if (kt + 1 < KT) {
            issue(kt + 1, cur ^ 1);
            CP_COMMIT();
            CP_WAIT1();
        } else {
            CP_WAIT0();
        }
        __syncthreads();

        const float* Ab = smf + cur * BUF;
        const float* Bb = Ab + ASZ;
#pragma unroll
        for (int ks = 0; ks < 4; ks++) {
            const int c0 = (2 * ks) ^ asw;       // chunk for k = 8ks + t4
            const int c1 = (2 * ks + 1) ^ asw;   // chunk for k = 8ks + 4 + t4
            uint32_t ah[MT][4], al[MT][4];
#pragma unroll
            for (int mt = 0; mt < MT; mt++) {
                int m0 = wm0 + mt * 16 + g;
                int m1 = m0 + 8;
                float v0 = ta(Ab[m0 * 32 + c0 * 4 + t4], m0, 2 * mt);
                float v1 = ta(Ab[m1 * 32 + c0 * 4 + t4], m1, 2 * mt + 1);
                float v2 = ta(Ab[m0 * 32 + c1 * 4 + t4], m0, 2 * mt);
                float v3 = ta(Ab[m1 * 32 + c1 * 4 + t4], m1, 2 * mt + 1);
                float h0 = tf32f(v0), h1 = tf32f(v1), h2 = tf32f(v2), h3 = tf32f(v3);
                ah[mt][0] = __float_as_uint(h0); al[mt][0] = tf32b(v0 - h0);
                ah[mt][1] = __float_as_uint(h1); al[mt][1] = tf32b(v1 - h1);
                ah[mt][2] = __float_as_uint(h2); al[mt][2] = tf32b(v2 - h2);
                ah[mt][3] = __float_as_uint(h3); al[mt][3] = tf32b(v3 - h3);
            }
#pragma unroll
            for (int nt = 0; nt < NT; nt++) {
                int n0 = wn0 + nt * 8 + g;
                float w0 = Bb[n0 * 32 + c0 * 4 + t4];
                float w1 = Bb[n0 * 32 + c1 * 4 + t4];
                float h0 = tf32f(w0), h1 = tf32f(w1);
                uint32_t bh[2], bl[2];
                bh[0] = __float_as_uint(h0); bl[0] = tf32b(w0 - h0);
                bh[1] = __float_as_uint(h1); bl[1] = tf32b(w1 - h1);
#pragma unroll
                for (int mt = 0; mt < MT; mt++) {
                    mma8(acc[mt][nt], ah[mt], bh);
                    mma8(acc[mt][nt], ah[mt], bl);
                    mma8(acc[mt][nt], al[mt], bh);
                }
            }
        }
        __syncthreads();
    }

    pe();   // pre-epilogue hook

    // epilogue: pair stores (col, col+1)
#pragma unroll
    for (int mt = 0; mt < MT; mt++) {
#pragma unroll
        for (int nt = 0; nt < NT; nt++) {
            int row = bm + wm0 + mt * 16 + g;
            int col = bn + wn0 + nt * 8 + 2 * t4;
            sc(row, col, acc[mt][nt][0], acc[mt][nt][1], 2 * mt);
            sc(row + 8, col, acc[mt][nt][2], acc[mt][nt][3], 2 * mt + 1);
        }
    }
}

// ---------------- FFMA2 core (N=33 rel-table GEMM only) ---------------------
template <int BM, int BN, int BK, int TM, int TN, class LA, class LB, class SC>
__device__ __forceinline__ void gemm_ffma2(int M, int N, int K, LA la, LB lb, SC sc) {
    constexpr int TX = BN / TN;
    constexpr int TY = BM / TM;
    constexpr int NTHR = TX * TY;
    constexpr int LAN = BM * BK / NTHR;
    constexpr int LBN = BN * BK / NTHR;

    __shared__ float As[2][BK][BM + 4];
    __shared__ float Bs[2][BK][BN + 4];

    const int tid = threadIdx.x;
    const int tx = tid % TX;
    const int ty = tid / TX;
    const int bm = blockIdx.y * BM;
    const int bn = blockIdx.x * BN;

    unsigned long long acc[TM / 2][TN];
#pragma unroll
    for (int i = 0; i < TM / 2; i++)
#pragma unroll
        for (int j = 0; j < TN; j++) acc[i][j] = 0ull;

    float ra[LAN], rb[LBN];
    const int KT = (K + BK - 1) / BK;

    auto fetch = [&](int kt) {
#pragma unroll
        for (int l = 0; l < LAN; l++) {
            int i = tid + l * NTHR;
            int m = i / BK, k = i % BK;
            int gm = bm + m, gk = kt * BK + k;
            ra[l] = (gm < M && gk < K) ? la(gm, gk) : 0.f;
        }
#pragma unroll
        for (int l = 0; l < LBN; l++) {
            int i = tid + l * NTHR;
            int n = i / BK, k = i % BK;
            int gn = bn + n, gk = kt * BK + k;
            rb[l] = (gn < N && gk < K) ? lb(gn, gk) : 0.f;
        }
    };
    auto stage = [&](int b) {
#pragma unroll
        for (int l = 0; l < LAN; l++) {
            int i = tid + l * NTHR;
            As[b][i % BK][i / BK] = ra[l];
        }
#pragma unroll
        for (int l = 0; l < LBN; l++) {
            int i = tid + l * NTHR;
            Bs[b][i % BK][i / BK] = rb[l];
        }
    };

    fetch(0); stage(0); __syncthreads();

    for (int kt = 0; kt < KT; kt++) {
        const int cur = kt & 1;
        if (kt + 1 < KT) fetch(kt + 1);
#pragma unroll
        for (int kk = 0; kk < BK; kk++) {
            unsigned long long a2[TM / 2];
            const ulonglong2* ap =
                reinterpret_cast<const ulonglong2*>(&As[cur][kk][ty * TM]);
#pragma unroll
            for (int i = 0; i < TM / 4; i++) {
                ulonglong2 t = ap[i];
                a2[2 * i] = t.x; a2[2 * i + 1] = t.y;
            }
            float b[TN];
            const float4* bp = reinterpret_cast<const float4*>(&Bs[cur][kk][tx * TN]);
#pragma unroll
            for (int j = 0; j < TN / 4; j++) {
                float4 t = bp[j];
                b[4 * j] = t.x; b[4 * j + 1] = t.y; b[4 * j + 2] = t.z; b[4 * j + 3] = t.w;
            }
#pragma unroll
            for (int j = 0; j < TN; j++) {
                unsigned long long bd = pk2(b[j], b[j]);
#pragma unroll
                for (int i = 0; i < TM / 2; i++) fma2(acc[i][j], a2[i], bd);
            }
        }
        if (kt + 1 < KT) stage((kt + 1) & 1);
        __syncthreads();
    }

#pragma unroll
    for (int i = 0; i < TM / 2; i++) {
        int gm0 = bm + ty * TM + 2 * i;
#pragma unroll
        for (int j = 0; j < TN; j++) {
            int gn = bn + tx * TN + j;
            if (gn >= N) continue;
            float lo, hi;
            upk2(acc[i][j], lo, hi);
            if (gm0 < M) sc(gm0, gn, lo);
            if (gm0 + 1 < M) sc(gm0 + 1, gn, hi);
        }
    }
}

// ---------------- kernels ----------------------------------------------------

#define TA_ID [&](float v, int, int) { return v; }
#define PE_NOP [&]() {}

// init row-max buffer (encoded -inf = 0u)
__global__ void k_initmax() {
    g_rowmax[(size_t)blockIdx.x * 1024 + threadIdx.x] = 0u;
}

// merged BPE projections: blockIdx.z = mode (0=q, 1=k, 2=v)
__global__ void __launch_bounds__(128, 3)
k_proj_bpe(const float* __restrict__ X,
           const float* __restrict__ Wq, const float* __restrict__ bq,
           const float* __restrict__ Wk, const float* __restrict__ bk,
           const float* __restrict__ Wv, const float* __restrict__ bv) {
    const int mode = blockIdx.z;
    const float* W = (mode == 0) ? Wq : (mode == 1) ? Wk : Wv;
    const float* bias = (mode == 0) ? bq : (mode == 1) ? bk : bv;
    const float scale = (mode == 0) ? SCALE_Q : 1.f;
    auto pa4 = [&](int m, int k4) { return &X[(size_t)m * E_DIM + k4 * 4]; };
    auto pb4 = [&](int n, int k4) { return &W[(size_t)n * E_DIM + k4 * 4]; };
    auto sc = [&](int m, int n, float v0, float v1, int) {
        int t = m >> 2, b = m & 3;
        int h = n >> 6, d = n & 63;      // n even; n, n+1 same head
        int nn = b * H_HEADS + h;
        float r0 = (v0 + bias[n]) * scale;
        float r1 = (v1 + bias[n + 1]) * scale;
        if (mode == 0)
            *(float2*)&g_qb[((size_t)nn * TBQ + t) * D_HEAD + d] = make_float2(r0, r1);
        else if (mode == 1)
            *(float2*)&g_kb[((size_t)nn * TBQ + t) * D_HEAD + d] = make_float2(r0, r1);
        else {
            g_vT[((size_t)nn * D_HEAD + d) * TBQ + t] = r0;
            g_vT[((size_t)nn * D_HEAD + d + 1) * TBQ + t] = r1;
        }
    };
    gemm_mma3<128, 64, 128, 64, 32>(E_DIM, pa4, pb4, TA_ID, PE_NOP, sc);
}

// merged word projections: blockIdx.z = mode (0=q, 1=k)
__global__ void __launch_bounds__(128, 3)
k_proj_word(const float* __restrict__ X,
            const float* __restrict__ Wq, const float* __restrict__ bq,
            const float* __restrict__ Wk, const float* __restrict__ bk) {
    const int mode = blockIdx.z;
    const float* W = (mode == 0) ? Wq : Wk;
    const float* bias = (mode == 0) ? bq : bk;
    const float scale = (mode == 0) ? SCALE_Q : 1.f;
    auto pa4 = [&](int m, int k4) { return &X[(size_t)m * E_DIM + k4 * 4]; };
    auto pb4 = [&](int n, int k4) { return &W[(size_t)n * E_DIM + k4 * 4]; };
    auto sc = [&](int m, int n, float v0, float v1, int) {
        int t = m >> 2, b = m & 3;
        int h = n >> 6, d = n & 63;
        int nn = b * H_HEADS + h;
        float r0 = (v0 + bias[n]) * scale;
        float r1 = (v1 + bias[n + 1]) * scale;
        float* dst = (mode == 0) ? g_qw : g_kw;
        *(float2*)&dst[((size_t)nn * TWQ + t) * D_HEAD + d] = make_float2(r0, r1);
    };
    gemm_mma3<128, 64, 128, 64, 32>(E_DIM, pa4, pb4, TA_ID, PE_NOP, sc);
}

// rel tables: N=33 -> FFMA2 core (BN=64)
__global__ void __launch_bounds__(128)
k_allr(const float* __restrict__ table, int mode) {
    int Mrows = (mode == 0) ? NH * TBQ : NH * TWQ;
    const float* Q = (mode == 0) ? g_qb : g_qw;
    float* out = (mode == 0) ? g_arb : g_arw;
    auto la = [&](int m, int k) { return Q[(size_t)m * D_HEAD + k]; };
    auto lb = [&](int n, int k) { return table[n * D_HEAD + k]; };
    auto sc = [&](int m, int n, float v) { out[(size_t)m * NR + n] = v; };
    gemm_ffma2<128, 64, 16, 8, 8>(Mrows, NR, D_HEAD, la, lb, sc);
}

// AWT[n,s,w] = q_word[n,w,:].k_word[n,s,:] + arw[n,w,clip(s-w)] (transposed store)
__global__ void __launch_bounds__(128, 3) k_attn_word() {
    int n = blockIdx.z;
    const float* qw = &g_qw[(size_t)n * TWQ * D_HEAD];
    const float* kw = &g_kw[(size_t)n * TWQ * D_HEAD];
    const float* arw = &g_arw[(size_t)n * TWQ * NR];
    float* out = &g_awt[(size_t)n * TWQ * TWQ];
    auto pa4 = [&](int s, int k4) { return &kw[s * D_HEAD + k4 * 4]; };
    auto pb4 = [&](int w, int k4) { return &qw[w * D_HEAD + k4 * 4]; };
    auto sc = [&](int s, int w, float v0, float v1, int) {
        float r0 = v0 + arw[w * NR + clip_rel(s - w)];
        float r1 = v1 + arw[(w + 1) * NR + clip_rel(s - w - 1)];
        *(float2*)&out[(size_t)s * TWQ + w] = make_float2(r0, r1);
    };
    gemm_mma3<128, 64, 128, 64, 32>(D_HEAD, pa4, pb4, TA_ID, PE_NOP, sc);
}

// G[n,q,s] = sum_w mapping[b,q,w] * AWT[n,s,w]
__global__ void __launch_bounds__(128, 3) k_G(const float* __restrict__ mapping) {
    int n = blockIdx.z;
    int b = n >> 4;
    const float* Mb = &mapping[(size_t)b * TBQ * TWQ];
    const float* awt = &g_awt[(size_t)n * TWQ * TWQ];
    float* out = &g_G[(size_t)n * TBQ * TWQ];
    auto pa4 = [&](int q, int k4) { return &Mb[(size_t)q * TWQ + k4 * 4]; };
    auto pb4 = [&](int s, int k4) { return &awt[(size_t)s * TWQ + k4 * 4]; };
    auto sc = [&](int q, int s, float v0, float v1, int) {
        *(float2*)&out[(size_t)q * TWQ + s] = make_float2(v0, v1);
    };
    gemm_mma3<128, 64, 128, 64, 32>(TWQ, pa4, pb4, TA_ID, PE_NOP, sc);
}

// attn[n,q,kc] = q.k (K=64) + G.mapping^T (K=512) + arb[q, clip(kc-q)]
// + free per-row max into g_rowmax (encoded, atomicMax)
__global__ void __launch_bounds__(128, 3) k_attn(const float* __restrict__ mapping) {
    int n = blockIdx.z;
    int b = n >> 4;
    const float* qb = &g_qb[(size_t)n * TBQ * D_HEAD];
    const float* kb = &g_kb[(size_t)n * TBQ * D_HEAD];
    const float* G = &g_G[(size_t)n * TBQ * TWQ];
    const float* Mb = &mapping[(size_t)b * TBQ * TWQ];
    const float* arb = &g_arb[(size_t)n * TBQ * NR];
    float* out = &g_attn[(size_t)n * TBQ * TBQ];

    float lmax[8];
#pragma unroll
    for (int j = 0; j < 8; j++) lmax[j] = -1e30f;

    auto pa4 = [&](int q, int k4) {
        int k = k4 * 4;
        return (k < D_HEAD) ? &qb[q * D_HEAD + k]
                            : &G[(size_t)q * TWQ + (k - D_HEAD)];
    };
    auto pb4 = [&](int kc, int k4) {
        int k = k4 * 4;
        return (k < D_HEAD) ? &kb[kc * D_HEAD + k]
                            : &Mb[(size_t)kc * TWQ + (k - D_HEAD)];
    };
    auto sc = [&](int q, int kc, float v0, float v1, int j) {
        float lv0 = v0 + arb[q * NR + clip_rel(kc - q)];
        float lv1 = v1 + arb[q * NR + clip_rel(kc + 1 - q)];
        *(float2*)&out[(size_t)q * TBQ + kc] = make_float2(lv0, lv1);
        lmax[j] = fmaxf(lmax[j], fmaxf(lv0, lv1));
    };
    gemm_mma3<128, 64, 128, 64, 32>(D_HEAD + TWQ, pa4, pb4, TA_ID, PE_NOP, sc);

    // reduce row maxima over 4-lane k-groups, then merge globally
    const int lane = threadIdx.x & 31;
    const int g = lane >> 2;
    const int t4 = lane & 3;
#pragma unroll
    for (int j = 0; j < 8; j++) {
        lmax[j] = fmaxf(lmax[j], __shfl_xor_sync(0xFFFFFFFFu, lmax[j], 1));
        lmax[j] = fmaxf(lmax[j], __shfl_xor_sync(0xFFFFFFFFu, lmax[j], 2));
    }
    if (t4 == 0) {
        unsigned* rm = &g_rowmax[(size_t)n * TBQ + blockIdx.y * 64];
#pragma unroll
        for (int j = 0; j < 8; j++) atomicMax(&rm[g + 8 * j], fenc(lmax[j]));
    }
}

// fused softmax + (probs @ V), single pass over g_attn:
// row max from g_rowmax; Z accumulated inside the A-transform; sc normalizes.
__global__ void __launch_bounds__(128) k_sctx() {
    constexpr int STATS_OFF = 2 * (64 + 64) * 32;   // floats, after pipeline bufs
    extern __shared__ float smf[];
    float* sm_m = smf + STATS_OFF;       // [64] row max
    float* sm_z = sm_m + 64;             // [64] row sum of exp

    const int n = blockIdx.z;
    const float* P = &g_attn[(size_t)n * TBQ * TBQ];
    const float* vT = &g_vT[(size_t)n * D_HEAD * TBQ];
    float* out = &g_ctx[(size_t)n * TBQ * D_HEAD];

    const int tid = threadIdx.x;
    const int lane = tid & 31;
    const int wid = tid >> 5;
    const int g = lane >> 2;
    const int t4 = lane & 3;
    const int wm0 = (wid & 1) * 32;
    const int bm = blockIdx.y * 64;

    if (tid < 64)
        sm_m[tid] = fdec(g_rowmax[(size_t)n * TBQ + bm + tid]);
    // (core's first __syncthreads orders these writes before any ta read)

    float z[4] = {0.f, 0.f, 0.f, 0.f};

    auto pa4 = [&](int q, int k4) { return &P[(size_t)q * TBQ + k4 * 4]; };
    auto pb4 = [&](int d, int k4) { return &vT[(size_t)d * TBQ + k4 * 4]; };
    auto ta = [&](float v, int lrow, int j) {
        float e = __expf(v - sm_m[lrow]);
        z[j] += e;
        return e;
    };
    auto pe = [&]() {
#pragma unroll
        for (int j = 0; j < 4; j++) {
            z[j] += __shfl_xor_sync(0xFFFFFFFFu, z[j], 1);
            z[j] += __shfl_xor_sync(0xFFFFFFFFu, z[j], 2);
        }
        if (wid < 2 && t4 == 0) {
#pragma unroll
            for (int j = 0; j < 4; j++) sm_z[wm0 + g + 8 * j] = z[j];
        }
        __syncthreads();
    };
    auto sc = [&](int q, int d, float v0, float v1, int) {
        float inv = 1.f / sm_z[q - bm];
        *(float2*)&out[(size_t)q * D_HEAD + d] = make_float2(v0 * inv, v1 * inv);
    };
    gemm_mma3<128, 64, 64, 32, 32>(TBQ, pa4, pb4, ta, pe, sc);
}

// out[t,b,e] = sum_{e'} ctx_heads[t,b,e'] * Wo[e,e'] + bo[e]
__global__ void __launch_bounds__(128, 3)
k_out(const float* __restrict__ Wo, const float* __restrict__ bo,
      float* __restrict__ out) {
    auto pa4 = [&](int m, int k4) {
        int k = k4 * 4;
        int t = m >> 2, b = m & 3;
        int nn = b * H_HEADS + (k >> 6);
        int d = k & 63;
        return &g_ctx[((size_t)nn * TBQ + t) * D_HEAD + d];
    };
    auto pb4 = [&](int e, int k4) { return &Wo[(size_t)e * E_DIM + k4 * 4]; };
    auto sc = [&](int m, int e, float v0, float v1, int) {
        *(float2*)&out[(size_t)m * E_DIM + e] =
            make_float2(v0 + bo[e], v1 + bo[e + 1]);
    };
    gemm_mma3<128, 64, 128, 64, 32>(E_DIM, pa4, pb4, TA_ID, PE_NOP, sc);
}

// ---------------- launch ------------------------------------------------------
// dynamic smem: 2 buffers * (BM + BN) * 32 floats * 4B (+ stats for k_sctx)
static const int SMEM_B64x128 = 2 * (64 + 128) * 32 * 4;     // 49152
static const int SMEM_SCTX = 2 * (64 + 64) * 32 * 4 + 512;   // 33280

extern "C" void kernel_launch(void* const* d_in, const int* in_sizes, int n_in,
                              void* d_out, int out_size) {
    const float* query_bpe  = (const float*)d_in[0];
    const float* query_word = (const float*)d_in[1];
    const float* mapping    = (const float*)d_in[2];
    const float* Wq_bpe  = (const float*)d_in[3];
    const float* bq_bpe  = (const float*)d_in[4];
    const float* Wk_bpe  = (const float*)d_in[5];
    const float* bk_bpe  = (const float*)d_in[6];
    const float* Wq_word = (const float*)d_in[7];
    const float* bq_word = (const float*)d_in[8];
    const float* Wk_word = (const float*)d_in[9];
    const float* bk_word = (const float*)d_in[10];
    const float* Wv = (const float*)d_in[11];
    const float* bv = (const float*)d_in[12];
    const float* Wo = (const float*)d_in[13];
    const float* bo = (const float*)d_in[14];
    const float* rel_keys = (const float*)d_in[15];
    float* out = (float*)d_out;

    static bool init_done = false;
    static cudaStream_t s1, s2;
    static cudaEvent_t eF1, eF2, e1, e2;
    if (!init_done) {
        cudaFuncSetAttribute(k_proj_bpe, cudaFuncAttributeMaxDynamicSharedMemorySize, SMEM_B64x128);
        cudaFuncSetAttribute(k_proj_word, cudaFuncAttributeMaxDynamicSharedMemorySize, SMEM_B64x128);
        cudaFuncSetAttribute(k_attn_word, cudaFuncAttributeMaxDynamicSharedMemorySize, SMEM_B64x128);
        cudaFuncSetAttribute(k_G, cudaFuncAttributeMaxDynamicSharedMemorySize, SMEM_B64x128);
        cudaFuncSetAttribute(k_attn, cudaFuncAttributeMaxDynamicSharedMemorySize, SMEM_B64x128);
        cudaFuncSetAttribute(k_sctx, cudaFuncAttributeMaxDynamicSharedMemorySize, SMEM_SCTX);
        cudaFuncSetAttribute(k_out, cudaFuncAttributeMaxDynamicSharedMemorySize, SMEM_B64x128);
        cudaStreamCreateWithFlags(&s1, cudaStreamNonBlocking);
        cudaStreamCreateWithFlags(&s2, cudaStreamNonBlocking);
        cudaEventCreateWithFlags(&eF1, cudaEventDisableTiming);
        cudaEventCreateWithFlags(&eF2, cudaEventDisableTiming);
        cudaEventCreateWithFlags(&e1, cudaEventDisableTiming);
        cudaEventCreateWithFlags(&e2, cudaEventDisableTiming);
        init_done = true;
    }

    // ---- fork: bring s1 (word chain) and s2 (initmax) into the graph ----
    cudaEventRecord(eF1, 0);
    cudaStreamWaitEvent(s1, eF1, 0);
    cudaEventRecord(eF2, 0);
    cudaStreamWaitEvent(s2, eF2, 0);

    // chain C (s2): row-max init (independent until k_attn)
    k_initmax<<<NH, 1024, 0, s2>>>();
    cudaEventRecord(e2, s2);

    // chain B (s1): word projections -> rel table -> word logits -> G
    k_proj_word<<<dim3(8, 32, 2), 128, SMEM_B64x128, s1>>>(query_word, Wq_word, bq_word,
                                                           Wk_word, bk_word);
    k_allr<<<dim3(1, 256), 128, 0, s1>>>(rel_keys, 1);
    k_attn_word<<<dim3(4, 8, NH), 128, SMEM_B64x128, s1>>>();
    k_G<<<dim3(4, 16, NH), 128, SMEM_B64x128, s1>>>(mapping);
    cudaEventRecord(e1, s1);

    // chain A (main stream): BPE projections -> rel table
    k_proj_bpe<<<dim3(8, 64, 3), 128, SMEM_B64x128>>>(query_bpe, Wq_bpe, bq_bpe,
                                                      Wk_bpe, bk_bpe, Wv, bv);
    k_allr<<<dim3(1, 512), 128>>>(rel_keys, 0);

    // ---- join: k_attn needs chain A + G (s1) + initmax (s2) ----
    cudaStreamWaitEvent(0, e1, 0);
    cudaStreamWaitEvent(0, e2, 0);

    k_attn<<<dim3(8, 16, NH), 128, SMEM_B64x128>>>(mapping);

    // fused softmax + probs @ V (single g_attn pass), then output projection
    k_sctx<<<dim3(1, 16, NH), 128, SMEM_SCTX>>>();
    k_out<<<dim3(8, 64), 128, SMEM_B64x128>>>(Wo, bo, out);
}

// round 16
// speedup vs baseline: 1.0412x; 1.0412x over previous
#include <cuda_runtime.h>
#include <cstdint>
#include <math.h>

#define E_DIM 1024
#define H_HEADS 16
#define D_HEAD 64
#define B_BATCH 4
#define TBQ 1024
#define TWQ 512
#define NH 64            // B_BATCH * H_HEADS
#define NR 33            // 2L+1
#define SCALE_Q 0.125f   // D^-0.5

// ---------------- scratch (device globals; no dynamic allocation) ----------
__device__ float g_qb[(size_t)NH * TBQ * D_HEAD];   // [n, t, d]
__device__ float g_kb[(size_t)NH * TBQ * D_HEAD];   // [n, t, d]
__device__ float g_vT[(size_t)NH * D_HEAD * TBQ];   // [n, d, t]
__device__ float g_qw[(size_t)NH * TWQ * D_HEAD];   // [n, w, d]
__device__ float g_kw[(size_t)NH * TWQ * D_HEAD];   // [n, w, d]
__device__ float g_arb[(size_t)NH * TBQ * NR];      // q_bpe . table
__device__ float g_arw[(size_t)NH * TWQ * NR];      // q_word . table
__device__ float g_awt[(size_t)NH * TWQ * TWQ];     // attn_word TRANSPOSED: [n, s, w]
__device__ float g_G[(size_t)NH * TBQ * TWQ];       // mapping @ attn_word: [n, q, s]
__device__ float g_attn[(size_t)NH * TBQ * TBQ];    // raw logits (256MB)
__device__ float g_ctx[(size_t)NH * TBQ * D_HEAD];  // softmax(attn) @ v
__device__ unsigned g_rowmax[(size_t)NH * TBQ];     // encoded per-row logit max

// ---------------- helpers -----------------------------------------------------
__device__ __forceinline__ uint32_t smem_u32(const void* p) {
    uint32_t a;
    asm("{ .reg .u64 t; cvta.to.shared.u64 t, %1; cvt.u32.u64 %0, t; }"
        : "=r"(a) : "l"(p));
    return a;
}
__device__ __forceinline__ float tf32f(float x) {
    uint32_t r;
    asm("cvt.rna.tf32.f32 %0, %1;" : "=r"(r) : "f"(x));
    return __uint_as_float(r);
}
__device__ __forceinline__ uint32_t tf32b(float x) {
    uint32_t r;
    asm("cvt.rna.tf32.f32 %0, %1;" : "=r"(r) : "f"(x));
    return r;
}
__device__ __forceinline__ int clip_rel(int d) {
    return (d < -16 ? -16 : (d > 16 ? 16 : d)) + 16;
}
// monotone float<->uint encoding for atomicMax on floats
__device__ __forceinline__ unsigned fenc(float x) {
    int b = __float_as_int(x);
    return (b >= 0) ? ((unsigned)b | 0x80000000u) : ~(unsigned)b;
}
__device__ __forceinline__ float fdec(unsigned k) {
    int b = (k & 0x80000000u) ? (int)(k & 0x7FFFFFFFu) : ~(int)k;
    return __int_as_float(b);
}
// streaming 16B copy: L2-only (.cg)
__device__ __forceinline__ void cpa16(uint32_t saddr, const float* gaddr) {
    asm volatile("cp.async.cg.shared.global [%0], [%1], 16;"
                 :: "r"(saddr), "l"(gaddr) : "memory");
}
#define CP_COMMIT() asm volatile("cp.async.commit_group;" ::: "memory")
#define CP_WAIT1() asm volatile("cp.async.wait_group 1;" ::: "memory")
#define CP_WAIT0() asm volatile("cp.async.wait_group 0;" ::: "memory")

// mma.sync tf32 m16n8k8 (baseline PTX -> HMMA on sm_103)
__device__ __forceinline__ void mma8(float* c, const uint32_t* a, const uint32_t* b) {
    asm volatile(
        "mma.sync.aligned.m16n8k8.row.col.f32.tf32.tf32.f32 "
        "{%0,%1,%2,%3}, {%4,%5,%6,%7}, {%8,%9}, {%0,%1,%2,%3};"
        : "+f"(c[0]), "+f"(c[1]), "+f"(c[2]), "+f"(c[3])
        : "r"(a[0]), "r"(a[1]), "r"(a[2]), "r"(a[3]), "r"(b[0]), "r"(b[1]));
}

// packed f32x2 (FFMA2) for the fallback core
__device__ __forceinline__ unsigned long long pk2(float x, float y) {
    unsigned long long r;
    asm("mov.b64 %0, {%1, %2};" : "=l"(r) : "f"(x), "f"(y));
    return r;
}
__device__ __forceinline__ void upk2(unsigned long long v, float& x, float& y) {
    asm("mov.b64 {%0, %1}, %2;" : "=f"(x), "=f"(y) : "l"(v));
}
__device__ __forceinline__ void fma2(unsigned long long& c, unsigned long long a,
                                     unsigned long long b) {
    asm("fma.rn.f32x2 %0, %1, %2, %0;" : "+l"(c) : "l"(a), "l"(b));
}

// ---------------- mma.sync 3xTF32 NT GEMM core v4 (BK=32, pair stores) --------
// C[m][n] = sum_k ta(A[m,k], m_local, j)*B[n,k], ~fp32 via 3xTF32 split.
// M % BM == 0, N % BN == 0, K % 32 == 0. BK = 32.
// pa4/pb4: const float* to 16B chunk (row, k4), global k4 index (k = 4*k4).
// ta(v, local_row, j): A transform; j = compile-time row-slot.
// pe(): after k-loop, before epilogue.
// sc(m, n, v0, v1, j): store PAIR at (m,n),(m,n+1); j = compile-time row-slot.
// smem: raw fp32, 32 floats/row, 3-bit chunk swizzle:
//   chunk' = k4 ^ ((row>>1)&3) ^ ((row&1)<<2)   (conflict-free both sides)
// cp.async double-buffered. NTHR threads.
template <int NTHR, int BM, int BN, int WM, int WN,
          class PA, class PB, class TA, class PE, class SC>
__device__ __forceinline__ void gemm_mma3(int K, PA pa4, PB pb4, TA ta, PE pe, SC sc) {
    constexpr int ASZ = BM * 32;           // floats
    constexpr int BSZ = BN * 32;
    constexpr int BUF = ASZ + BSZ;
    constexpr int ACH = BM * 8;            // 16B chunks
    constexpr int BCH = BN * 8;
    constexpr int MT = WM / 16;
    constexpr int NT = WN / 8;
    constexpr int WGM = BM / WM;
    static_assert((BM / WM) * (BN / WN) == NTHR / 32, "warp grid");
    static_assert(ACH % NTHR == 0 && BCH % NTHR == 0, "fetch split");

    extern __shared__ float smf[];
    const uint32_t sbase = smem_u32(smf);

    const int tid = threadIdx.x;
    const int lane = tid & 31;
    const int wid = tid >> 5;
    const int wm0 = (wid % WGM) * WM;
    const int wn0 = (wid / WGM) * WN;
    const int bm = blockIdx.y * BM;
    const int bn = blockIdx.x * BN;
    const int g = lane >> 2;
    const int t4 = lane & 3;
    const int asw = ((g >> 1) & 3) | ((g & 1) << 2);   // 3-bit frag swizzle mask

    float acc[MT][NT][4];
#pragma unroll
    for (int i = 0; i < MT; i++)
#pragma unroll
        for (int j = 0; j < NT; j++) {
            acc[i][j][0] = 0.f; acc[i][j][1] = 0.f;
            acc[i][j][2] = 0.f; acc[i][j][3] = 0.f;
        }

    const int KT = K / 32;

    auto issue = [&](int kt, int buf) {
        uint32_t ab = sbase + buf * (BUF * 4);
        uint32_t bb = ab + ASZ * 4;
#pragma unroll
        for (int l = 0; l < ACH / NTHR; l++) {
            int f = tid + l * NTHR;
            int row = f >> 3, k4 = f & 7;
            int sw = k4 ^ ((row >> 1) & 3) ^ ((row & 1) << 2);
            cpa16(ab + (row * 8 + sw) * 16, pa4(bm + row, kt * 8 + k4));
        }
#pragma unroll
        for (int l = 0; l < BCH / NTHR; l++) {
            int f = tid + l * NTHR;
            int row = f >> 3, k4 = f & 7;
            int sw = k4 ^ ((row >> 1) & 3) ^ ((row & 1) << 2);
            cpa16(bb + (row * 8 + sw) * 16, pb4(bn + row, kt * 8 + k4));
        }
    };

    issue(0, 0);
    CP_COMMIT();

    for (int kt = 0; kt < KT; kt++) {
        const int cur = kt & 1;
        if (kt + 1 < KT) {
            issue(kt + 1, cur ^ 1);
            CP_COMMIT();
            CP_WAIT1();
        } else {
            CP_WAIT0();
        }
        __syncthreads();

        const float* Ab = smf + cur * BUF;
        const float* Bb = Ab + ASZ;
#pragma unroll
        for (int ks = 0; ks < 4; ks++) {
            const int c0 = (2 * ks) ^ asw;       // chunk for k = 8ks + t4
            const int c1 = (2 * ks + 1) ^ asw;   // chunk for k = 8ks + 4 + t4
            uint32_t ah[MT][4], al[MT][4];
#pragma unroll
            for (int mt = 0; mt < MT; mt++) {
                int m0 = wm0 + mt * 16 + g;
                int m1 = m0 + 8;
                float v0 = ta(Ab[m0 * 32 + c0 * 4 + t4], m0, 2 * mt);
                float v1 = ta(Ab[m1 * 32 + c0 * 4 + t4], m1, 2 * mt + 1);
                float v2 = ta(Ab[m0 * 32 + c1 * 4 + t4], m0, 2 * mt);
                float v3 = ta(Ab[m1 * 32 + c1 * 4 + t4], m1, 2 * mt + 1);
                float h0 = tf32f(v0), h1 = tf32f(v1), h2 = tf32f(v2), h3 = tf32f(v3);
                ah[mt][0] = __float_as_uint(h0); al[mt][0] = tf32b(v0 - h0);
                ah[mt][1] = __float_as_uint(h1); al[mt][1] = tf32b(v1 - h1);
                ah[mt][2] = __float_as_uint(h2); al[mt][2] = tf32b(v2 - h2);
                ah[mt][3] = __float_as_uint(h3); al[mt][3] = tf32b(v3 - h3);
            }
#pragma unroll
            for (int nt = 0; nt < NT; nt++) {
                int n0 = wn0 + nt * 8 + g;
                float w0 = Bb[n0 * 32 + c0 * 4 + t4];
                float w1 = Bb[n0 * 32 + c1 * 4 + t4];
                float h0 = tf32f(w0), h1 = tf32f(w1);
                uint32_t bh[2], bl[2];
                bh[0] = __float_as_uint(h0); bl[0] = tf32b(w0 - h0);
                bh[1] = __float_as_uint(h1); bl[1] = tf32b(w1 - h1);
#pragma unroll
                for (int mt = 0; mt < MT; mt++) {
                    mma8(acc[mt][nt], ah[mt], bh);
                    mma8(acc[mt][nt], ah[mt], bl);
                    mma8(acc[mt][nt], al[mt], bh);
                }
            }
        }
        __syncthreads();
    }

    pe();   // pre-epilogue hook

    // epilogue: pair stores (col, col+1)
#pragma unroll
    for (int mt = 0; mt < MT; mt++) {
#pragma unroll
        for (int nt = 0; nt < NT; nt++) {
            int row = bm + wm0 + mt * 16 + g;
            int col = bn + wn0 + nt * 8 + 2 * t4;
            sc(row, col, acc[mt][nt][0], acc[mt][nt][1], 2 * mt);
            sc(row + 8, col, acc[mt][nt][2], acc[mt][nt][3], 2 * mt + 1);
        }
    }
}

// ---------------- FFMA2 core (N=33 rel-table GEMM only) ---------------------
template <int BM, int BN, int BK, int TM, int TN, class LA, class LB, class SC>
__device__ __forceinline__ void gemm_ffma2(int M, int N, int K, LA la, LB lb, SC sc) {
    constexpr int TX = BN / TN;
    constexpr int TY = BM / TM;
    constexpr int NTHR = TX * TY;
    constexpr int LAN = BM * BK / NTHR;
    constexpr int LBN = BN * BK / NTHR;

    __shared__ float As[2][BK][BM + 4];
    __shared__ float Bs[2][BK][BN + 4];

    const int tid = threadIdx.x;
    const int tx = tid % TX;
    const int ty = tid / TX;
    const int bm = blockIdx.y * BM;
    const int bn = blockIdx.x * BN;

    unsigned long long acc[TM / 2][TN];
#pragma unroll
    for (int i = 0; i < TM / 2; i++)
#pragma unroll
        for (int j = 0; j < TN; j++) acc[i][j] = 0ull;

    float ra[LAN], rb[LBN];
    const int KT = (K + BK - 1) / BK;

    auto fetch = [&](int kt) {
#pragma unroll
        for (int l = 0; l < LAN; l++) {
            int i = tid + l * NTHR;
            int m = i / BK, k = i % BK;
            int gm = bm + m, gk = kt * BK + k;
            ra[l] = (gm < M && gk < K) ? la(gm, gk) : 0.f;
        }
#pragma unroll
        for (int l = 0; l < LBN; l++) {
            int i = tid + l * NTHR;
            int n = i / BK, k = i % BK;
            int gn = bn + n, gk = kt * BK + k;
            rb[l] = (gn < N && gk < K) ? lb(gn, gk) : 0.f;
        }
    };
    auto stage = [&](int b) {
#pragma unroll
        for (int l = 0; l < LAN; l++) {
            int i = tid + l * NTHR;
            As[b][i % BK][i / BK] = ra[l];
        }
#pragma unroll
        for (int l = 0; l < LBN; l++) {
            int i = tid + l * NTHR;
            Bs[b][i % BK][i / BK] = rb[l];
        }
    };

    fetch(0); stage(0); __syncthreads();

    for (int kt = 0; kt < KT; kt++) {
        const int cur = kt & 1;
        if (kt + 1 < KT) fetch(kt + 1);
#pragma unroll
        for (int kk = 0; kk < BK; kk++) {
            unsigned long long a2[TM / 2];
            const ulonglong2* ap =
                reinterpret_cast<const ulonglong2*>(&As[cur][kk][ty * TM]);
#pragma unroll
            for (int i = 0; i < TM / 4; i++) {
                ulonglong2 t = ap[i];
                a2[2 * i] = t.x; a2[2 * i + 1] = t.y;
            }
            float b[TN];
            const float4* bp = reinterpret_cast<const float4*>(&Bs[cur][kk][tx * TN]);
#pragma unroll
            for (int j = 0; j < TN / 4; j++) {
                float4 t = bp[j];
                b[4 * j] = t.x; b[4 * j + 1] = t.y; b[4 * j + 2] = t.z; b[4 * j + 3] = t.w;
            }
#pragma unroll
            for (int j = 0; j < TN; j++) {
                unsigned long long bd = pk2(b[j], b[j]);
#pragma unroll
                for (int i = 0; i < TM / 2; i++) fma2(acc[i][j], a2[i], bd);
            }
        }
        if (kt + 1 < KT) stage((kt + 1) & 1);
        __syncthreads();
    }

#pragma unroll
    for (int i = 0; i < TM / 2; i++) {
        int gm0 = bm + ty * TM + 2 * i;
#pragma unroll
        for (int j = 0; j < TN; j++) {
            int gn = bn + tx * TN + j;
            if (gn >= N) continue;
            float lo, hi;
            upk2(acc[i][j], lo, hi);
            if (gm0 < M) sc(gm0, gn, lo);
            if (gm0 + 1 < M) sc(gm0 + 1, gn, hi);
        }
    }
}

// ---------------- kernels ----------------------------------------------------

#define TA_ID [&](float v, int, int) { return v; }
#define PE_NOP [&]() {}

// init row-max buffer (encoded -inf = 0u)
__global__ void k_initmax() {
    g_rowmax[(size_t)blockIdx.x * 1024 + threadIdx.x] = 0u;
}

// merged BPE projections: blockIdx.z = mode (0=q, 1=k, 2=v)
__global__ void __launch_bounds__(128)
k_proj_bpe(const float* __restrict__ X,
           const float* __restrict__ Wq, const float* __restrict__ bq,
           const float* __restrict__ Wk, const float* __restrict__ bk,
           const float* __restrict__ Wv, const float* __restrict__ bv) {
    const int mode = blockIdx.z;
    const float* W = (mode == 0) ? Wq : (mode == 1) ? Wk : Wv;
    const float* bias = (mode == 0) ? bq : (mode == 1) ? bk : bv;
    const float scale = (mode == 0) ? SCALE_Q : 1.f;
    auto pa4 = [&](int m, int k4) { return &X[(size_t)m * E_DIM + k4 * 4]; };
    auto pb4 = [&](int n, int k4) { return &W[(size_t)n * E_DIM + k4 * 4]; };
    auto sc = [&](int m, int n, float v0, float v1, int) {
        int t = m >> 2, b = m & 3;
        int h = n >> 6, d = n & 63;      // n even; n, n+1 same head
        int nn = b * H_HEADS + h;
        float r0 = (v0 + bias[n]) * scale;
        float r1 = (v1 + bias[n + 1]) * scale;
        if (mode == 0)
            *(float2*)&g_qb[((size_t)nn * TBQ + t) * D_HEAD + d] = make_float2(r0, r1);
        else if (mode == 1)
            *(float2*)&g_kb[((size_t)nn * TBQ + t) * D_HEAD + d] = make_float2(r0, r1);
        else {
            g_vT[((size_t)nn * D_HEAD + d) * TBQ + t] = r0;
            g_vT[((size_t)nn * D_HEAD + d + 1) * TBQ + t] = r1;
        }
    };
    gemm_mma3<128, 64, 256, 64, 64>(E_DIM, pa4, pb4, TA_ID, PE_NOP, sc);
}

// merged word projections: blockIdx.z = mode (0=q, 1=k)
__global__ void __launch_bounds__(128)
k_proj_word(const float* __restrict__ X,
            const float* __restrict__ Wq, const float* __restrict__ bq,
            const float* __restrict__ Wk, const float* __restrict__ bk) {
    const int mode = blockIdx.z;
    const float* W = (mode == 0) ? Wq : Wk;
    const float* bias = (mode == 0) ? bq : bk;
    const float scale = (mode == 0) ? SCALE_Q : 1.f;
    auto pa4 = [&](int m, int k4) { return &X[(size_t)m * E_DIM + k4 * 4]; };
    auto pb4 = [&](int n, int k4) { return &W[(size_t)n * E_DIM + k4 * 4]; };
    auto sc = [&](int m, int n, float v0, float v1, int) {
        int t = m >> 2, b = m & 3;
        int h = n >> 6, d = n & 63;
        int nn = b * H_HEADS + h;
        float r0 = (v0 + bias[n]) * scale;
        float r1 = (v1 + bias[n + 1]) * scale;
        float* dst = (mode == 0) ? g_qw : g_kw;
        *(float2*)&dst[((size_t)nn * TWQ + t) * D_HEAD + d] = make_float2(r0, r1);
    };
    gemm_mma3<128, 64, 256, 64, 64>(E_DIM, pa4, pb4, TA_ID, PE_NOP, sc);
}

// rel tables: N=33 -> FFMA2 core (BN=64)
__global__ void __launch_bounds__(128)
k_allr(const float* __restrict__ table, int mode) {
    int Mrows = (mode == 0) ? NH * TBQ : NH * TWQ;
    const float* Q = (mode == 0) ? g_qb : g_qw;
    float* out = (mode == 0) ? g_arb : g_arw;
    auto la = [&](int m, int k) { return Q[(size_t)m * D_HEAD + k]; };
    auto lb = [&](int n, int k) { return table[n * D_HEAD + k]; };
    auto sc = [&](int m, int n, float v) { out[(size_t)m * NR + n] = v; };
    gemm_ffma2<128, 64, 16, 8, 8>(Mrows, NR, D_HEAD, la, lb, sc);
}

// AWT[n,s,w] = q_word[n,w,:].k_word[n,s,:] + arw[n,w,clip(s-w)] (transposed store)
__global__ void __launch_bounds__(128) k_attn_word() {
    int n = blockIdx.z;
    const float* qw = &g_qw[(size_t)n * TWQ * D_HEAD];
    const float* kw = &g_kw[(size_t)n * TWQ * D_HEAD];
    const float* arw = &g_arw[(size_t)n * TWQ * NR];
    float* out = &g_awt[(size_t)n * TWQ * TWQ];
    auto pa4 = [&](int s, int k4) { return &kw[s * D_HEAD + k4 * 4]; };
    auto pb4 = [&](int w, int k4) { return &qw[w * D_HEAD + k4 * 4]; };
    auto sc = [&](int s, int w, float v0, float v1, int) {
        float r0 = v0 + arw[w * NR + clip_rel(s - w)];
        float r1 = v1 + arw[(w + 1) * NR + clip_rel(s - w - 1)];
        *(float2*)&out[(size_t)s * TWQ + w] = make_float2(r0, r1);
    };
    gemm_mma3<128, 64, 256, 64, 64>(D_HEAD, pa4, pb4, TA_ID, PE_NOP, sc);
}

// G[n,q,s] = sum_w mapping[b,q,w] * AWT[n,s,w]
__global__ void __launch_bounds__(128) k_G(const float* __restrict__ mapping) {
    int n = blockIdx.z;
    int b = n >> 4;
    const float* Mb = &mapping[(size_t)b * TBQ * TWQ];
    const float* awt = &g_awt[(size_t)n * TWQ * TWQ];
    float* out = &g_G[(size_t)n * TBQ * TWQ];
    auto pa4 = [&](int q, int k4) { return &Mb[(size_t)q * TWQ + k4 * 4]; };
    auto pb4 = [&](int s, int k4) { return &awt[(size_t)s * TWQ + k4 * 4]; };
    auto sc = [&](int q, int s, float v0, float v1, int) {
        *(float2*)&out[(size_t)q * TWQ + s] = make_float2(v0, v1);
    };
    gemm_mma3<128, 64, 256, 64, 64>(TWQ, pa4, pb4, TA_ID, PE_NOP, sc);
}

// attn[n,q,kc] = q.k (K=64) + G.mapping^T (K=512) + arb[q, clip(kc-q)]
// + free per-row max into g_rowmax. n = blockIdx.z + nb0 (head-half split).
__global__ void __launch_bounds__(128) k_attn(const float* __restrict__ mapping, int nb0) {
    int n = blockIdx.z + nb0;
    int b = n >> 4;
    const float* qb = &g_qb[(size_t)n * TBQ * D_HEAD];
    const float* kb = &g_kb[(size_t)n * TBQ * D_HEAD];
    const float* G = &g_G[(size_t)n * TBQ * TWQ];
    const float* Mb = &mapping[(size_t)b * TBQ * TWQ];
    const float* arb = &g_arb[(size_t)n * TBQ * NR];
    float* out = &g_attn[(size_t)n * TBQ * TBQ];

    float lmax[8];
#pragma unroll
    for (int j = 0; j < 8; j++) lmax[j] = -1e30f;

    auto pa4 = [&](int q, int k4) {
        int k = k4 * 4;
        return (k < D_HEAD) ? &qb[q * D_HEAD + k]
                            : &G[(size_t)q * TWQ + (k - D_HEAD)];
    };
    auto pb4 = [&](int kc, int k4) {
        int k = k4 * 4;
        return (k < D_HEAD) ? &kb[kc * D_HEAD + k]
                            : &Mb[(size_t)kc * TWQ + (k - D_HEAD)];
    };
    auto sc = [&](int q, int kc, float v0, float v1, int j) {
        float lv0 = v0 + arb[q * NR + clip_rel(kc - q)];
        float lv1 = v1 + arb[q * NR + clip_rel(kc + 1 - q)];
        *(float2*)&out[(size_t)q * TBQ + kc] = make_float2(lv0, lv1);
        lmax[j] = fmaxf(lmax[j], fmaxf(lv0, lv1));
    };
    gemm_mma3<128, 64, 256, 64, 64>(D_HEAD + TWQ, pa4, pb4, TA_ID, PE_NOP, sc);

    // reduce row maxima over 4-lane k-groups, then merge globally
    const int lane = threadIdx.x & 31;
    const int g = lane >> 2;
    const int t4 = lane & 3;
#pragma unroll
    for (int j = 0; j < 8; j++) {
        lmax[j] = fmaxf(lmax[j], __shfl_xor_sync(0xFFFFFFFFu, lmax[j], 1));
        lmax[j] = fmaxf(lmax[j], __shfl_xor_sync(0xFFFFFFFFu, lmax[j], 2));
    }
    if (t4 == 0) {
        unsigned* rm = &g_rowmax[(size_t)n * TBQ + blockIdx.y * 64];
#pragma unroll
        for (int j = 0; j < 8; j++) atomicMax(&rm[g + 8 * j], fenc(lmax[j]));
    }
}

// fused softmax + (probs @ V), single pass over g_attn:
// row max from g_rowmax; Z accumulated inside the A-transform; sc normalizes.
// n = blockIdx.z + nb0 (head-half split).
__global__ void __launch_bounds__(128) k_sctx(int nb0) {
    constexpr int STATS_OFF = 2 * (64 + 64) * 32;   // floats, after pipeline bufs
    extern __shared__ float smf[];
    float* sm_m = smf + STATS_OFF;       // [64] row max
    float* sm_z = sm_m + 64;             // [64] row sum of exp

    const int n = blockIdx.z + nb0;
    const float* P = &g_attn[(size_t)n * TBQ * TBQ];
    const float* vT = &g_vT[(size_t)n * D_HEAD * TBQ];
    float* out = &g_ctx[(size_t)n * TBQ * D_HEAD];

    const int tid = threadIdx.x;
    const int lane = tid & 31;
    const int wid = tid >> 5;
    const int g = lane >> 2;
    const int t4 = lane & 3;
    const int wm0 = (wid & 1) * 32;
    const int bm = blockIdx.y * 64;

    if (tid < 64)
        sm_m[tid] = fdec(g_rowmax[(size_t)n * TBQ + bm + tid]);
    // (core's first __syncthreads orders these writes before any ta read)

    float z[4] = {0.f, 0.f, 0.f, 0.f};

    auto pa4 = [&](int q, int k4) { return &P[(size_t)q * TBQ + k4 * 4]; };
    auto pb4 = [&](int d, int k4) { return &vT[(size_t)d * TBQ + k4 * 4]; };
    auto ta = [&](float v, int lrow, int j) {
        float e = __expf(v - sm_m[lrow]);
        z[j] += e;
        return e;
    };
    auto pe = [&]() {
#pragma unroll
        for (int j = 0; j < 4; j++) {
            z[j] += __shfl_xor_sync(0xFFFFFFFFu, z[j], 1);
            z[j] += __shfl_xor_sync(0xFFFFFFFFu, z[j], 2);
        }
        if (wid < 2 && t4 == 0) {
#pragma unroll
            for (int j = 0; j < 4; j++) sm_z[wm0 + g + 8 * j] = z[j];
        }
        __syncthreads();
    };
    auto sc = [&](int q, int d, float v0, float v1, int) {
        float inv = 1.f / sm_z[q - bm];
        *(float2*)&out[(size_t)q * D_HEAD + d] = make_float2(v0 * inv, v1 * inv);
    };
    gemm_mma3<128, 64, 64, 32, 32>(TBQ, pa4, pb4, ta, pe, sc);
}

// out[t,b,e] = sum_{e'} ctx_heads[t,b,e'] * Wo[e,e'] + bo[e]
__global__ void __launch_bounds__(128)
k_out(const float* __restrict__ Wo, const float* __restrict__ bo,
      float* __restrict__ out) {
    auto pa4 = [&](int m, int k4) {
        int k = k4 * 4;
        int t = m >> 2, b = m & 3;
        int nn = b * H_HEADS + (k >> 6);
        int d = k & 63;
        return &g_ctx[((size_t)nn * TBQ + t) * D_HEAD + d];
    };
    auto pb4 = [&](int e, int k4) { return &Wo[(size_t)e * E_DIM + k4 * 4]; };
    auto sc = [&](int m, int e, float v0, float v1, int) {
        *(float2*)&out[(size_t)m * E_DIM + e] =
            make_float2(v0 + bo[e], v1 + bo[e + 1]);
    };
    gemm_mma3<128, 64, 256, 64, 64>(E_DIM, pa4, pb4, TA_ID, PE_NOP, sc);
}

// ---------------- launch ------------------------------------------------------
// dynamic smem: 2 buffers * (BM + BN) * 32 floats * 4B (+ stats for k_sctx)
static const int SMEM_B64x256 = 2 * (64 + 256) * 32 * 4;     // 81920
static const int SMEM_SCTX = 2 * (64 + 64) * 32 * 4 + 512;   // 33280

extern "C" void kernel_launch(void* const* d_in, const int* in_sizes, int n_in,
                              void* d_out, int out_size) {
    const float* query_bpe  = (const float*)d_in[0];
    const float* query_word = (const float*)d_in[1];
    const float* mapping    = (const float*)d_in[2];
    const float* Wq_bpe  = (const float*)d_in[3];
    const float* bq_bpe  = (const float*)d_in[4];
    const float* Wk_bpe  = (const float*)d_in[5];
    const float* bk_bpe  = (const float*)d_in[6];
    const float* Wq_word = (const float*)d_in[7];
    const float* bq_word = (const float*)d_in[8];
    const float* Wk_word = (const float*)d_in[9];
    const float* bk_word = (const float*)d_in[10];
    const float* Wv = (const float*)d_in[11];
    const float* bv = (const float*)d_in[12];
    const float* Wo = (const float*)d_in[13];
    const float* bo = (const float*)d_in[14];
    const float* rel_keys = (const float*)d_in[15];
    float* out = (float*)d_out;

    static bool init_done = false;
    static cudaStream_t s1, s2;
    static cudaEvent_t eF1, eF2, e1, e2, eA0, eS0;
    if (!init_done) {
        cudaFuncSetAttribute(k_proj_bpe, cudaFuncAttributeMaxDynamicSharedMemorySize, SMEM_B64x256);
        cudaFuncSetAttribute(k_proj_word, cudaFuncAttributeMaxDynamicSharedMemorySize, SMEM_B64x256);
        cudaFuncSetAttribute(k_attn_word, cudaFuncAttributeMaxDynamicSharedMemorySize, SMEM_B64x256);
        cudaFuncSetAttribute(k_G, cudaFuncAttributeMaxDynamicSharedMemorySize, SMEM_B64x256);
        cudaFuncSetAttribute(k_attn, cudaFuncAttributeMaxDynamicSharedMemorySize, SMEM_B64x256);
        cudaFuncSetAttribute(k_sctx, cudaFuncAttributeMaxDynamicSharedMemorySize, SMEM_SCTX);
        cudaFuncSetAttribute(k_out, cudaFuncAttributeMaxDynamicSharedMemorySize, SMEM_B64x256);
        cudaStreamCreateWithFlags(&s1, cudaStreamNonBlocking);
        cudaStreamCreateWithFlags(&s2, cudaStreamNonBlocking);
        cudaEventCreateWithFlags(&eF1, cudaEventDisableTiming);
        cudaEventCreateWithFlags(&eF2, cudaEventDisableTiming);
        cudaEventCreateWithFlags(&e1, cudaEventDisableTiming);
        cudaEventCreateWithFlags(&e2, cudaEventDisableTiming);
        cudaEventCreateWithFlags(&eA0, cudaEventDisableTiming);
        cudaEventCreateWithFlags(&eS0, cudaEventDisableTiming);
        init_done = true;
    }

    // ---- fork: bring s1 (word chain) and s2 (initmax) into the graph ----
    cudaEventRecord(eF1, 0);
    cudaStreamWaitEvent(s1, eF1, 0);
    cudaEventRecord(eF2, 0);
    cudaStreamWaitEvent(s2, eF2, 0);

    // chain C (s2): row-max init (independent until k_attn)
    k_initmax<<<NH, 1024, 0, s2>>>();
    cudaEventRecord(e2, s2);

    // chain B (s1): word projections -> rel table -> word logits -> G
    k_proj_word<<<dim3(4, 32, 2), 128, SMEM_B64x256, s1>>>(query_word, Wq_word, bq_word,
                                                           Wk_word, bk_word);
    k_allr<<<dim3(1, 256), 128, 0, s1>>>(rel_keys, 1);
    k_attn_word<<<dim3(2, 8, NH), 128, SMEM_B64x256, s1>>>();
    k_G<<<dim3(2, 16, NH), 128, SMEM_B64x256, s1>>>(mapping);
    cudaEventRecord(e1, s1);

    // chain A (main stream): BPE projections -> rel table
    k_proj_bpe<<<dim3(4, 64, 3), 128, SMEM_B64x256>>>(query_bpe, Wq_bpe, bq_bpe,
                                                      Wk_bpe, bk_bpe, Wv, bv);
    k_allr<<<dim3(1, 512), 128>>>(rel_keys, 0);

    // ---- join: k_attn needs chain A + G (s1) + initmax (s2) ----
    cudaStreamWaitEvent(0, e1, 0);
    cudaStreamWaitEvent(0, e2, 0);

    // head-half pipeline: sctx(h0) on s1 overlaps attn(h1) on main
    k_attn<<<dim3(4, 16, NH / 2), 128, SMEM_B64x256>>>(mapping, 0);
    cudaEventRecord(eA0, 0);
    k_attn<<<dim3(4, 16, NH / 2), 128, SMEM_B64x256>>>(mapping, NH / 2);

    cudaStreamWaitEvent(s1, eA0, 0);
    k_sctx<<<dim3(1, 16, NH / 2), 128, SMEM_SCTX, s1>>>(0);
    cudaEventRecord(eS0, s1);

    k_sctx<<<dim3(1, 16, NH / 2), 128, SMEM_SCTX>>>(NH / 2);

    cudaStreamWaitEvent(0, eS0, 0);
    k_out<<<dim3(4, 64), 128, SMEM_B64x256>>>(Wo, bo, out);
}

// round 17
// speedup vs baseline: 1.0471x; 1.0056x over previous
#include <cuda_runtime.h>
#include <cstdint>
#include <math.h>

#define E_DIM 1024
#define H_HEADS 16
#define D_HEAD 64
#define B_BATCH 4
#define TBQ 1024
#define TWQ 512
#define NH 64            // B_BATCH * H_HEADS
#define NR 33            // 2L+1
#define SCALE_Q 0.125f   // D^-0.5

// ---------------- scratch (device globals; no dynamic allocation) ----------
__device__ float g_qb[(size_t)NH * TBQ * D_HEAD];   // [n, t, d]
__device__ float g_kb[(size_t)NH * TBQ * D_HEAD];   // [n, t, d]
__device__ float g_vT[(size_t)NH * D_HEAD * TBQ];   // [n, d, t]
__device__ float g_qw[(size_t)NH * TWQ * D_HEAD];   // [n, w, d]
__device__ float g_kw[(size_t)NH * TWQ * D_HEAD];   // [n, w, d]
__device__ float g_arb[(size_t)NH * TBQ * NR];      // q_bpe . table
__device__ float g_arw[(size_t)NH * TWQ * NR];      // q_word . table
__device__ float g_awt[(size_t)NH * TWQ * TWQ];     // attn_word TRANSPOSED: [n, s, w]
__device__ float g_G[(size_t)NH * TBQ * TWQ];       // mapping @ attn_word: [n, q, s]
__device__ float g_attn[(size_t)NH * TBQ * TBQ];    // raw logits (256MB)
__device__ float g_ctx[(size_t)NH * TBQ * D_HEAD];  // softmax(attn) @ v
__device__ unsigned g_rowmax[(size_t)NH * TBQ];     // encoded per-row logit max

// ---------------- helpers -----------------------------------------------------
__device__ __forceinline__ uint32_t smem_u32(const void* p) {
    uint32_t a;
    asm("{ .reg .u64 t; cvta.to.shared.u64 t, %1; cvt.u32.u64 %0, t; }"
        : "=r"(a) : "l"(p));
    return a;
}
__device__ __forceinline__ float tf32f(float x) {
    uint32_t r;
    asm("cvt.rna.tf32.f32 %0, %1;" : "=r"(r) : "f"(x));
    return __uint_as_float(r);
}
__device__ __forceinline__ uint32_t tf32b(float x) {
    uint32_t r;
    asm("cvt.rna.tf32.f32 %0, %1;" : "=r"(r) : "f"(x));
    return r;
}
__device__ __forceinline__ int clip_rel(int d) {
    return (d < -16 ? -16 : (d > 16 ? 16 : d)) + 16;
}
// monotone float<->uint encoding for atomicMax on floats
__device__ __forceinline__ unsigned fenc(float x) {
    int b = __float_as_int(x);
    return (b >= 0) ? ((unsigned)b | 0x80000000u) : ~(unsigned)b;
}
__device__ __forceinline__ float fdec(unsigned k) {
    int b = (k & 0x80000000u) ? (int)(k & 0x7FFFFFFFu) : ~(int)k;
    return __int_as_float(b);
}
// streaming 16B copy: L2-only (.cg)
__device__ __forceinline__ void cpa16(uint32_t saddr, const float* gaddr) {
    asm volatile("cp.async.cg.shared.global [%0], [%1], 16;"
                 :: "r"(saddr), "l"(gaddr) : "memory");
}
#define CP_COMMIT() asm volatile("cp.async.commit_group;" ::: "memory")
#define CP_WAIT1() asm volatile("cp.async.wait_group 1;" ::: "memory")
#define CP_WAIT0() asm volatile("cp.async.wait_group 0;" ::: "memory")

// mma.sync tf32 m16n8k8 (baseline PTX -> HMMA on sm_103)
__device__ __forceinline__ void mma8(float* c, const uint32_t* a, const uint32_t* b) {
    asm volatile(
        "mma.sync.aligned.m16n8k8.row.col.f32.tf32.tf32.f32 "
        "{%0,%1,%2,%3}, {%4,%5,%6,%7}, {%8,%9}, {%0,%1,%2,%3};"
        : "+f"(c[0]), "+f"(c[1]), "+f"(c[2]), "+f"(c[3])
        : "r"(a[0]), "r"(a[1]), "r"(a[2]), "r"(a[3]), "r"(b[0]), "r"(b[1]));
}

// packed f32x2 (FFMA2) for the fallback core
__device__ __forceinline__ unsigned long long pk2(float x, float y) {
    unsigned long long r;
    asm("mov.b64 %0, {%1, %2};" : "=l"(r) : "f"(x), "f"(y));
    return r;
}
__device__ __forceinline__ void upk2(unsigned long long v, float& x, float& y) {
    asm("mov.b64 {%0, %1}, %2;" : "=f"(x), "=f"(y) : "l"(v));
}
__device__ __forceinline__ void fma2(unsigned long long& c, unsigned long long a,
                                     unsigned long long b) {
    asm("fma.rn.f32x2 %0, %1, %2, %0;" : "+l"(c) : "l"(a), "l"(b));
}

// ---------------- mma.sync 3xTF32 NT GEMM core v4 (BK=32, pair stores) --------
// C[m][n] = sum_k ta(A[m,k], m_local, j)*B[n,k], ~fp32 via 3xTF32 split.
// M % BM == 0, N % BN == 0, K % 32 == 0. BK = 32.
// pa4/pb4: const float* to 16B chunk (row, k4), global k4 index (k = 4*k4).
// ta(v, local_row, j): A transform; j = compile-time row-slot.
// pe(): after k-loop, before epilogue.
// sc(m, n, v0, v1, j): store PAIR at (m,n),(m,n+1); j = compile-time row-slot.
// smem: raw fp32, 32 floats/row, 3-bit chunk swizzle:
//   chunk' = k4 ^ ((row>>1)&3) ^ ((row&1)<<2)   (conflict-free both sides)
// cp.async double-buffered. NTHR threads.
template <int NTHR, int BM, int BN, int WM, int WN,
          class PA, class PB, class TA, class PE, class SC>
__device__ __forceinline__ void gemm_mma3(int K, PA pa4, PB pb4, TA ta, PE pe, SC sc) {
    constexpr int ASZ = BM * 32;           // floats
    constexpr int BSZ = BN * 32;
    constexpr int BUF = ASZ + BSZ;
    constexpr int ACH = BM * 8;            // 16B chunks
    constexpr int BCH = BN * 8;
    constexpr int MT = WM / 16;
    constexpr int NT = WN / 8;
    constexpr int WGM = BM / WM;
    static_assert((BM / WM) * (BN / WN) == NTHR / 32, "warp grid");
    static_assert(ACH % NTHR == 0 && BCH % NTHR == 0, "fetch split");

    extern __shared__ float smf[];
    const uint32_t sbase = smem_u32(smf);

    const int tid = threadIdx.x;
    const int lane = tid & 31;
    const int wid = tid >> 5;
    const int wm0 = (wid % WGM) * WM;
    const int wn0 = (wid / WGM) * WN;
    const int bm = blockIdx.y * BM;
    const int bn = blockIdx.x * BN;
    const int g = lane >> 2;
    const int t4 = lane & 3;
    const int asw = ((g >> 1) & 3) | ((g & 1) << 2);   // 3-bit frag swizzle mask

    float acc[MT][NT][4];
#pragma unroll
    for (int i = 0; i < MT; i++)
#pragma unroll
        for (int j = 0; j < NT; j++) {
            acc[i][j][0] = 0.f; acc[i][j][1] = 0.f;
            acc[i][j][2] = 0.f; acc[i][j][3] = 0.f;
        }

    const int KT = K / 32;

    auto issue = [&](int kt, int buf) {
        uint32_t ab = sbase + buf * (BUF * 4);
        uint32_t bb = ab + ASZ * 4;
#pragma unroll
        for (int l = 0; l < ACH / NTHR; l++) {
            int f = tid + l * NTHR;
            int row = f >> 3, k4 = f & 7;
            int sw = k4 ^ ((row >> 1) & 3) ^ ((row & 1) << 2);
            cpa16(ab + (row * 8 + sw) * 16, pa4(bm + row, kt * 8 + k4));
        }
#pragma unroll
        for (int l = 0; l < BCH / NTHR; l++) {
            int f = tid + l * NTHR;
            int row = f >> 3, k4 = f & 7;
            int sw = k4 ^ ((row >> 1) & 3) ^ ((row & 1) << 2);
            cpa16(bb + (row * 8 + sw) * 16, pb4(bn + row, kt * 8 + k4));
        }
    };

    issue(0, 0);
    CP_COMMIT();

    for (int kt = 0; kt < KT; kt++) {
        const int cur = kt & 1;
        if (kt + 1 < KT) {
            issue(kt + 1, cur ^ 1);
            CP_COMMIT();
            CP_WAIT1();
        } else {
            CP_WAIT0();
        }
        __syncthreads();

        const float* Ab = smf + cur * BUF;
        const float* Bb = Ab + ASZ;
#pragma unroll
        for (int ks = 0; ks < 4; ks++) {
            const int c0 = (2 * ks) ^ asw;       // chunk for k = 8ks + t4
            const int c1 = (2 * ks + 1) ^ asw;   // chunk for k = 8ks + 4 + t4
            uint32_t ah[MT][4], al[MT][4];
#pragma unroll
            for (int mt = 0; mt < MT; mt++) {
                int m0 = wm0 + mt * 16 + g;
                int m1 = m0 + 8;
                float v0 = ta(Ab[m0 * 32 + c0 * 4 + t4], m0, 2 * mt);
                float v1 = ta(Ab[m1 * 32 + c0 * 4 + t4], m1, 2 * mt + 1);
                float v2 = ta(Ab[m0 * 32 + c1 * 4 + t4], m0, 2 * mt);
                float v3 = ta(Ab[m1 * 32 + c1 * 4 + t4], m1, 2 * mt + 1);
                float h0 = tf32f(v0), h1 = tf32f(v1), h2 = tf32f(v2), h3 = tf32f(v3);
                ah[mt][0] = __float_as_uint(h0); al[mt][0] = tf32b(v0 - h0);
                ah[mt][1] = __float_as_uint(h1); al[mt][1] = tf32b(v1 - h1);
                ah[mt][2] = __float_as_uint(h2); al[mt][2] = tf32b(v2 - h2);
                ah[mt][3] = __float_as_uint(h3); al[mt][3] = tf32b(v3 - h3);
            }
#pragma unroll
            for (int nt = 0; nt < NT; nt++) {
                int n0 = wn0 + nt * 8 + g;
                float w0 = Bb[n0 * 32 + c0 * 4 + t4];
                float w1 = Bb[n0 * 32 + c1 * 4 + t4];
                float h0 = tf32f(w0), h1 = tf32f(w1);
                uint32_t bh[2], bl[2];
                bh[0] = __float_as_uint(h0); bl[0] = tf32b(w0 - h0);
                bh[1] = __float_as_uint(h1); bl[1] = tf32b(w1 - h1);
#pragma unroll
                for (int mt = 0; mt < MT; mt++) {
                    mma8(acc[mt][nt], ah[mt], bh);
                    mma8(acc[mt][nt], ah[mt], bl);
                    mma8(acc[mt][nt], al[mt], bh);
                }
            }
        }
        __syncthreads();
    }

    pe();   // pre-epilogue hook

    // epilogue: pair stores (col, col+1)
#pragma unroll
    for (int mt = 0; mt < MT; mt++) {
#pragma unroll
        for (int nt = 0; nt < NT; nt++) {
            int row = bm + wm0 + mt * 16 + g;
            int col = bn + wn0 + nt * 8 + 2 * t4;
            sc(row, col, acc[mt][nt][0], acc[mt][nt][1], 2 * mt);
            sc(row + 8, col, acc[mt][nt][2], acc[mt][nt][3], 2 * mt + 1);
        }
    }
}

// ---------------- FFMA2 core (N=33 rel-table GEMM only) ---------------------
template <int BM, int BN, int BK, int TM, int TN, class LA, class LB, class SC>
__device__ __forceinline__ void gemm_ffma2(int M, int N, int K, LA la, LB lb, SC sc) {
    constexpr int TX = BN / TN;
    constexpr int TY = BM / TM;
    constexpr int NTHR = TX * TY;
    constexpr int LAN = BM * BK / NTHR;
    constexpr int LBN = BN * BK / NTHR;

    __shared__ float As[2][BK][BM + 4];
    __shared__ float Bs[2][BK][BN + 4];

    const int tid = threadIdx.x;
    const int tx = tid % TX;
    const int ty = tid / TX;
    const int bm = blockIdx.y * BM;
    const int bn = blockIdx.x * BN;

    unsigned long long acc[TM / 2][TN];
#pragma unroll
    for (int i = 0; i < TM / 2; i++)
#pragma unroll
        for (int j = 0; j < TN; j++) acc[i][j] = 0ull;

    float ra[LAN], rb[LBN];
    const int KT = (K + BK - 1) / BK;

    auto fetch = [&](int kt) {
#pragma unroll
        for (int l = 0; l < LAN; l++) {
            int i = tid + l * NTHR;
            int m = i / BK, k = i % BK;
            int gm = bm + m, gk = kt * BK + k;
            ra[l] = (gm < M && gk < K) ? la(gm, gk) : 0.f;
        }
#pragma unroll
        for (int l = 0; l < LBN; l++) {
            int i = tid + l * NTHR;
            int n = i / BK, k = i % BK;
            int gn = bn + n, gk = kt * BK + k;
            rb[l] = (gn < N && gk < K) ? lb(gn, gk) : 0.f;
        }
    };
    auto stage = [&](int b) {
#pragma unroll
        for (int l = 0; l < LAN; l++) {
            int i = tid + l * NTHR;
            As[b][i % BK][i / BK] = ra[l];
        }
#pragma unroll
        for (int l = 0; l < LBN; l++) {
            int i = tid + l * NTHR;
            Bs[b][i % BK][i / BK] = rb[l];
        }
    };

    fetch(0); stage(0); __syncthreads();

    for (int kt = 0; kt < KT; kt++) {
        const int cur = kt & 1;
        if (kt + 1 < KT) fetch(kt + 1);
#pragma unroll
        for (int kk = 0; kk < BK; kk++) {
            unsigned long long a2[TM / 2];
            const ulonglong2* ap =
                reinterpret_cast<const ulonglong2*>(&As[cur][kk][ty * TM]);
#pragma unroll
            for (int i = 0; i < TM / 4; i++) {
                ulonglong2 t = ap[i];
                a2[2 * i] = t.x; a2[2 * i + 1] = t.y;
            }
            float b[TN];
            const float4* bp = reinterpret_cast<const float4*>(&Bs[cur][kk][tx * TN]);
#pragma unroll
            for (int j = 0; j < TN / 4; j++) {
                float4 t = bp[j];
                b[4 * j] = t.x; b[4 * j + 1] = t.y; b[4 * j + 2] = t.z; b[4 * j + 3] = t.w;
            }
#pragma unroll
            for (int j = 0; j < TN; j++) {
                unsigned long long bd = pk2(b[j], b[j]);
#pragma unroll
                for (int i = 0; i < TM / 2; i++) fma2(acc[i][j], a2[i], bd);
            }
        }
        if (kt + 1 < KT) stage((kt + 1) & 1);
        __syncthreads();
    }

#pragma unroll
    for (int i = 0; i < TM / 2; i++) {
        int gm0 = bm + ty * TM + 2 * i;
#pragma unroll
        for (int j = 0; j < TN; j++) {
            int gn = bn + tx * TN + j;
            if (gn >= N) continue;
            float lo, hi;
            upk2(acc[i][j], lo, hi);
            if (gm0 < M) sc(gm0, gn, lo);
            if (gm0 + 1 < M) sc(gm0 + 1, gn, hi);
        }
    }
}

// ---------------- kernels ----------------------------------------------------

#define TA_ID [&](float v, int, int) { return v; }
#define PE_NOP [&]() {}

// init row-max buffer (encoded -inf = 0u)
__global__ void k_initmax() {
    g_rowmax[(size_t)blockIdx.x * 1024 + threadIdx.x] = 0u;
}

// merged BPE projections: blockIdx.z = mode (0=q, 1=k, 2=v)
__global__ void __launch_bounds__(128)
k_proj_bpe(const float* __restrict__ X,
           const float* __restrict__ Wq, const float* __restrict__ bq,
           const float* __restrict__ Wk, const float* __restrict__ bk,
           const float* __restrict__ Wv, const float* __restrict__ bv) {
    const int mode = blockIdx.z;
    const float* W = (mode == 0) ? Wq : (mode == 1) ? Wk : Wv;
    const float* bias = (mode == 0) ? bq : (mode == 1) ? bk : bv;
    const float scale = (mode == 0) ? SCALE_Q : 1.f;
    auto pa4 = [&](int m, int k4) { return &X[(size_t)m * E_DIM + k4 * 4]; };
    auto pb4 = [&](int n, int k4) { return &W[(size_t)n * E_DIM + k4 * 4]; };
    auto sc = [&](int m, int n, float v0, float v1, int) {
        int t = m >> 2, b = m & 3;
        int h = n >> 6, d = n & 63;      // n even; n, n+1 same head
        int nn = b * H_HEADS + h;
        float r0 = (v0 + bias[n]) * scale;
        float r1 = (v1 + bias[n + 1]) * scale;
        if (mode == 0)
            *(float2*)&g_qb[((size_t)nn * TBQ + t) * D_HEAD + d] = make_float2(r0, r1);
        else if (mode == 1)
            *(float2*)&g_kb[((size_t)nn * TBQ + t) * D_HEAD + d] = make_float2(r0, r1);
        else {
            g_vT[((size_t)nn * D_HEAD + d) * TBQ + t] = r0;
            g_vT[((size_t)nn * D_HEAD + d + 1) * TBQ + t] = r1;
        }
    };
    gemm_mma3<128, 128, 128, 64, 64>(E_DIM, pa4, pb4, TA_ID, PE_NOP, sc);
}

// merged word projections: blockIdx.z = mode (0=q, 1=k)
__global__ void __launch_bounds__(128)
k_proj_word(const float* __restrict__ X,
            const float* __restrict__ Wq, const float* __restrict__ bq,
            const float* __restrict__ Wk, const float* __restrict__ bk) {
    const int mode = blockIdx.z;
    const float* W = (mode == 0) ? Wq : Wk;
    const float* bias = (mode == 0) ? bq : bk;
    const float scale = (mode == 0) ? SCALE_Q : 1.f;
    auto pa4 = [&](int m, int k4) { return &X[(size_t)m * E_DIM + k4 * 4]; };
    auto pb4 = [&](int n, int k4) { return &W[(size_t)n * E_DIM + k4 * 4]; };
    auto sc = [&](int m, int n, float v0, float v1, int) {
        int t = m >> 2, b = m & 3;
        int h = n >> 6, d = n & 63;
        int nn = b * H_HEADS + h;
        float r0 = (v0 + bias[n]) * scale;
        float r1 = (v1 + bias[n + 1]) * scale;
        float* dst = (mode == 0) ? g_qw : g_kw;
        *(float2*)&dst[((size_t)nn * TWQ + t) * D_HEAD + d] = make_float2(r0, r1);
    };
    gemm_mma3<128, 128, 128, 64, 64>(E_DIM, pa4, pb4, TA_ID, PE_NOP, sc);
}

// rel tables: N=33 -> FFMA2 core (BN=64)
__global__ void __launch_bounds__(128)
k_allr(const float* __restrict__ table, int mode) {
    int Mrows = (mode == 0) ? NH * TBQ : NH * TWQ;
    const float* Q = (mode == 0) ? g_qb : g_qw;
    float* out = (mode == 0) ? g_arb : g_arw;
    auto la = [&](int m, int k) { return Q[(size_t)m * D_HEAD + k]; };
    auto lb = [&](int n, int k) { return table[n * D_HEAD + k]; };
    auto sc = [&](int m, int n, float v) { out[(size_t)m * NR + n] = v; };
    gemm_ffma2<128, 64, 16, 8, 8>(Mrows, NR, D_HEAD, la, lb, sc);
}

// AWT[n,s,w] = q_word[n,w,:].k_word[n,s,:] + arw[n,w,clip(s-w)] (transposed store)
__global__ void __launch_bounds__(128) k_attn_word() {
    int n = blockIdx.z;
    const float* qw = &g_qw[(size_t)n * TWQ * D_HEAD];
    const float* kw = &g_kw[(size_t)n * TWQ * D_HEAD];
    const float* arw = &g_arw[(size_t)n * TWQ * NR];
    float* out = &g_awt[(size_t)n * TWQ * TWQ];
    auto pa4 = [&](int s, int k4) { return &kw[s * D_HEAD + k4 * 4]; };
    auto pb4 = [&](int w, int k4) { return &qw[w * D_HEAD + k4 * 4]; };
    auto sc = [&](int s, int w, float v0, float v1, int) {
        float r0 = v0 + arw[w * NR + clip_rel(s - w)];
        float r1 = v1 + arw[(w + 1) * NR + clip_rel(s - w - 1)];
        *(float2*)&out[(size_t)s * TWQ + w] = make_float2(r0, r1);
    };
    gemm_mma3<128, 128, 128, 64, 64>(D_HEAD, pa4, pb4, TA_ID, PE_NOP, sc);
}

// G[n,q,s] = sum_w mapping[b,q,w] * AWT[n,s,w]
__global__ void __launch_bounds__(128) k_G(const float* __restrict__ mapping) {
    int n = blockIdx.z;
    int b = n >> 4;
    const float* Mb = &mapping[(size_t)b * TBQ * TWQ];
    const float* awt = &g_awt[(size_t)n * TWQ * TWQ];
    float* out = &g_G[(size_t)n * TBQ * TWQ];
    auto pa4 = [&](int q, int k4) { return &Mb[(size_t)q * TWQ + k4 * 4]; };
    auto pb4 = [&](int s, int k4) { return &awt[(size_t)s * TWQ + k4 * 4]; };
    auto sc = [&](int q, int s, float v0, float v1, int) {
        *(float2*)&out[(size_t)q * TWQ + s] = make_float2(v0, v1);
    };
    gemm_mma3<128, 128, 128, 64, 64>(TWQ, pa4, pb4, TA_ID, PE_NOP, sc);
}

// attn[n,q,kc] = q.k (K=64) + G.mapping^T (K=512) + arb[q, clip(kc-q)]
// + free per-row max into g_rowmax. n = blockIdx.z + nb0 (head-half split).
__global__ void __launch_bounds__(128) k_attn(const float* __restrict__ mapping, int nb0) {
    int n = blockIdx.z + nb0;
    int b = n >> 4;
    const float* qb = &g_qb[(size_t)n * TBQ * D_HEAD];
    const float* kb = &g_kb[(size_t)n * TBQ * D_HEAD];
    const float* G = &g_G[(size_t)n * TBQ * TWQ];
    const float* Mb = &mapping[(size_t)b * TBQ * TWQ];
    const float* arb = &g_arb[(size_t)n * TBQ * NR];
    float* out = &g_attn[(size_t)n * TBQ * TBQ];

    float lmax[8];
#pragma unroll
    for (int j = 0; j < 8; j++) lmax[j] = -1e30f;

    auto pa4 = [&](int q, int k4) {
        int k = k4 * 4;
        return (k < D_HEAD) ? &qb[q * D_HEAD + k]
                            : &G[(size_t)q * TWQ + (k - D_HEAD)];
    };
    auto pb4 = [&](int kc, int k4) {
        int k = k4 * 4;
        return (k < D_HEAD) ? &kb[kc * D_HEAD + k]
                            : &Mb[(size_t)kc * TWQ + (k - D_HEAD)];
    };
    auto sc = [&](int q, int kc, float v0, float v1, int j) {
        float lv0 = v0 + arb[q * NR + clip_rel(kc - q)];
        float lv1 = v1 + arb[q * NR + clip_rel(kc + 1 - q)];
        *(float2*)&out[(size_t)q * TBQ + kc] = make_float2(lv0, lv1);
        lmax[j] = fmaxf(lmax[j], fmaxf(lv0, lv1));
    };
    gemm_mma3<128, 128, 128, 64, 64>(D_HEAD + TWQ, pa4, pb4, TA_ID, PE_NOP, sc);

    // reduce row maxima over 4-lane k-groups, then merge globally.
    // rows for slot j: wm0 + 8*j + g  (wm0 = (wid&1)*64 with WGM=2);
    // both warp-columns (wn halves) atomicMax the same rows - commutative.
    const int lane = threadIdx.x & 31;
    const int wid = threadIdx.x >> 5;
    const int wm0 = (wid & 1) * 64;
    const int g = lane >> 2;
    const int t4 = lane & 3;
#pragma unroll
    for (int j = 0; j < 8; j++) {
        lmax[j] = fmaxf(lmax[j], __shfl_xor_sync(0xFFFFFFFFu, lmax[j], 1));
        lmax[j] = fmaxf(lmax[j], __shfl_xor_sync(0xFFFFFFFFu, lmax[j], 2));
    }
    if (t4 == 0) {
        unsigned* rm = &g_rowmax[(size_t)n * TBQ + blockIdx.y * 128 + wm0];
#pragma unroll
        for (int j = 0; j < 8; j++) atomicMax(&rm[g + 8 * j], fenc(lmax[j]));
    }
}

// fused softmax + (probs @ V), single pass over g_attn:
// row max from g_rowmax; Z accumulated inside the A-transform; sc normalizes.
// n = blockIdx.z + nb0 (head-half split).
__global__ void __launch_bounds__(128) k_sctx(int nb0) {
    constexpr int STATS_OFF = 2 * (64 + 64) * 32;   // floats, after pipeline bufs
    extern __shared__ float smf[];
    float* sm_m = smf + STATS_OFF;       // [64] row max
    float* sm_z = sm_m + 64;             // [64] row sum of exp

    const int n = blockIdx.z + nb0;
    const float* P = &g_attn[(size_t)n * TBQ * TBQ];
    const float* vT = &g_vT[(size_t)n * D_HEAD * TBQ];
    float* out = &g_ctx[(size_t)n * TBQ * D_HEAD];

    const int tid = threadIdx.x;
    const int lane = tid & 31;
    const int wid = tid >> 5;
    const int g = lane >> 2;
    const int t4 = lane & 3;
    const int wm0 = (wid & 1) * 32;
    const int bm = blockIdx.y * 64;

    if (tid < 64)
        sm_m[tid] = fdec(g_rowmax[(size_t)n * TBQ + bm + tid]);
    // (core's first __syncthreads orders these writes before any ta read)

    float z[4] = {0.f, 0.f, 0.f, 0.f};

    auto pa4 = [&](int q, int k4) { return &P[(size_t)q * TBQ + k4 * 4]; };
    auto pb4 = [&](int d, int k4) { return &vT[(size_t)d * TBQ + k4 * 4]; };
    auto ta = [&](float v, int lrow, int j) {
        float e = __expf(v - sm_m[lrow]);
        z[j] += e;
        return e;
    };
    auto pe = [&]() {
#pragma unroll
        for (int j = 0; j < 4; j++) {
            z[j] += __shfl_xor_sync(0xFFFFFFFFu, z[j], 1);
            z[j] += __shfl_xor_sync(0xFFFFFFFFu, z[j], 2);
        }
        if (wid < 2 && t4 == 0) {
#pragma unroll
            for (int j = 0; j < 4; j++) sm_z[wm0 + g + 8 * j] = z[j];
        }
        __syncthreads();
    };
    auto sc = [&](int q, int d, float v0, float v1, int) {
        float inv = 1.f / sm_z[q - bm];
        *(float2*)&out[(size_t)q * D_HEAD + d] = make_float2(v0 * inv, v1 * inv);
    };
    gemm_mma3<128, 64, 64, 32, 32>(TBQ, pa4, pb4, ta, pe, sc);
}

// out[t,b,e] = sum_{e'} ctx_heads[t,b,e'] * Wo[e,e'] + bo[e]
__global__ void __launch_bounds__(128)
k_out(const float* __restrict__ Wo, const float* __restrict__ bo,
      float* __restrict__ out) {
    auto pa4 = [&](int m, int k4) {
        int k = k4 * 4;
        int t = m >> 2, b = m & 3;
        int nn = b * H_HEADS + (k >> 6);
        int d = k & 63;
        return &g_ctx[((size_t)nn * TBQ + t) * D_HEAD + d];
    };
    auto pb4 = [&](int e, int k4) { return &Wo[(size_t)e * E_DIM + k4 * 4]; };
    auto sc = [&](int m, int e, float v0, float v1, int) {
        *(float2*)&out[(size_t)m * E_DIM + e] =
            make_float2(v0 + bo[e], v1 + bo[e + 1]);
    };
    gemm_mma3<128, 128, 128, 64, 64>(E_DIM, pa4, pb4, TA_ID, PE_NOP, sc);
}

// ---------------- launch ------------------------------------------------------
// dynamic smem: 2 buffers * (BM + BN) * 32 floats * 4B (+ stats for k_sctx)
static const int SMEM_B128x128 = 2 * (128 + 128) * 32 * 4;   // 65536
static const int SMEM_SCTX = 2 * (64 + 64) * 32 * 4 + 512;   // 33280

extern "C" void kernel_launch(void* const* d_in, const int* in_sizes, int n_in,
                              void* d_out, int out_size) {
    const float* query_bpe  = (const float*)d_in[0];
    const float* query_word = (const float*)d_in[1];
    const float* mapping    = (const float*)d_in[2];
    const float* Wq_bpe  = (const float*)d_in[3];
    const float* bq_bpe  = (const float*)d_in[4];
    const float* Wk_bpe  = (const float*)d_in[5];
    const float* bk_bpe  = (const float*)d_in[6];
    const float* Wq_word = (const float*)d_in[7];
    const float* bq_word = (const float*)d_in[8];
    const float* Wk_word = (const float*)d_in[9];
    const float* bk_word = (const float*)d_in[10];
    const float* Wv = (const float*)d_in[11];
    const float* bv = (const float*)d_in[12];
    const float* Wo = (const float*)d_in[13];
    const float* bo = (const float*)d_in[14];
    const float* rel_keys = (const float*)d_in[15];
    float* out = (float*)d_out;

    static bool init_done = false;
    static cudaStream_t s1, s2;
    static cudaEvent_t eF1, eF2, e1, e2, eA0, eS0;
    if (!init_done) {
        cudaFuncSetAttribute(k_proj_bpe, cudaFuncAttributeMaxDynamicSharedMemorySize, SMEM_B128x128);
        cudaFuncSetAttribute(k_proj_word, cudaFuncAttributeMaxDynamicSharedMemorySize, SMEM_B128x128);
        cudaFuncSetAttribute(k_attn_word, cudaFuncAttributeMaxDynamicSharedMemorySize, SMEM_B128x128);
        cudaFuncSetAttribute(k_G, cudaFuncAttributeMaxDynamicSharedMemorySize, SMEM_B128x128);
        cudaFuncSetAttribute(k_attn, cudaFuncAttributeMaxDynamicSharedMemorySize, SMEM_B128x128);
        cudaFuncSetAttribute(k_sctx, cudaFuncAttributeMaxDynamicSharedMemorySize, SMEM_SCTX);
        cudaFuncSetAttribute(k_out, cudaFuncAttributeMaxDynamicSharedMemorySize, SMEM_B128x128);
        cudaStreamCreateWithFlags(&s1, cudaStreamNonBlocking);
        cudaStreamCreateWithFlags(&s2, cudaStreamNonBlocking);
        cudaEventCreateWithFlags(&eF1, cudaEventDisableTiming);
        cudaEventCreateWithFlags(&eF2, cudaEventDisableTiming);
        cudaEventCreateWithFlags(&e1, cudaEventDisableTiming);
        cudaEventCreateWithFlags(&e2, cudaEventDisableTiming);
        cudaEventCreateWithFlags(&eA0, cudaEventDisableTiming);
        cudaEventCreateWithFlags(&eS0, cudaEventDisableTiming);
        init_done = true;
    }

    // ---- fork: bring s1 (word chain) and s2 (initmax) into the graph ----
    cudaEventRecord(eF1, 0);
    cudaStreamWaitEvent(s1, eF1, 0);
    cudaEventRecord(eF2, 0);
    cudaStreamWaitEvent(s2, eF2, 0);

    // chain C (s2): row-max init (independent until k_attn)
    k_initmax<<<NH, 1024, 0, s2>>>();
    cudaEventRecord(e2, s2);

    // chain B (s1): word projections -> rel table -> word logits -> G
    k_proj_word<<<dim3(8, 16, 2), 128, SMEM_B128x128, s1>>>(query_word, Wq_word, bq_word,
                                                            Wk_word, bk_word);
    k_allr<<<dim3(1, 256), 128, 0, s1>>>(rel_keys, 1);
    k_attn_word<<<dim3(4, 4, NH), 128, SMEM_B128x128, s1>>>();
    k_G<<<dim3(4, 8, NH), 128, SMEM_B128x128, s1>>>(mapping);
    cudaEventRecord(e1, s1);

    // chain A (main stream): BPE projections -> rel table
    k_proj_bpe<<<dim3(8, 32, 3), 128, SMEM_B128x128>>>(query_bpe, Wq_bpe, bq_bpe,
                                                       Wk_bpe, bk_bpe, Wv, bv);
    k_allr<<<dim3(1, 512), 128>>>(rel_keys, 0);

    // ---- join: k_attn needs chain A + G (s1) + initmax (s2) ----
    cudaStreamWaitEvent(0, e1, 0);
    cudaStreamWaitEvent(0, e2, 0);

    // head-half pipeline: sctx(h0) on s1 overlaps attn(h1) on main
    k_attn<<<dim3(8, 8, NH / 2), 128, SMEM_B128x128>>>(mapping, 0);
    cudaEventRecord(eA0, 0);
    k_attn<<<dim3(8, 8, NH / 2), 128, SMEM_B128x128>>>(mapping, NH / 2);

    cudaStreamWaitEvent(s1, eA0, 0);
    k_sctx<<<dim3(1, 16, NH / 2), 128, SMEM_SCTX, s1>>>(0);
    cudaEventRecord(eS0, s1);

    k_sctx<<<dim3(1, 16, NH / 2), 128, SMEM_SCTX>>>(NH / 2);

    cudaStreamWaitEvent(0, eS0, 0);
    k_out<<<dim3(8, 32), 128, SMEM_B128x128>>>(Wo, bo, out);
}